// round 1
// baseline (speedup 1.0000x reference)
#include <cuda_runtime.h>
#include <cuda_bf16.h>
#include <cstdint>

// Problem constants (from reference): B=8, T=128, D=256
#define BB 8
#define TT 128
#define DD 256

// Scratch for per-(b,t) partial contributions: partial[b][t][q]
__device__ float g_partial[BB * TT * DD];

__device__ __forceinline__ float ex2f(float x) {
    float y;
    asm("ex2.approx.f32 %0, %1;" : "=f"(y) : "f"(x));
    return y;
}

// Pass 1: one block per (b,t). Computes colsum/rowsum of M[p,q]=exp(d_p*e_q)
// and writes partial[b,t,q] = e_q * colsum[q] / rowsum[q].
__global__ __launch_bounds__(256) void attn_pass1(
    const float* __restrict__ dec,   // [B, D]
    const float* __restrict__ enc)   // [B, T, D]
{
    const int bt = blockIdx.x;           // 0..B*T-1
    const int b  = bt >> 7;              // /T (T=128)
    const int tid  = threadIdx.x;
    const int warp = tid >> 5;
    const int lane = tid & 31;

    __shared__ float sdl[DD];   // dec * log2(e)
    __shared__ float se[DD];    // enc row
    __shared__ float srow[DD];  // row sums
    __shared__ float scol[DD];  // col sums (atomic accumulated)

    sdl[tid] = dec[b * DD + tid] * 1.4426950408889634f;
    se[tid]  = enc[bt * DD + tid];
    scol[tid] = 0.0f;
    __syncthreads();

    // Warp w owns rows [32w, 32w+32), all 256 columns.
    // Lane l owns columns {l, l+32, ..., l+224}.
    const int p0 = warp << 5;

    float e8[8], colacc[8];
    #pragma unroll
    for (int k = 0; k < 8; k++) {
        e8[k] = se[lane + 32 * k];
        colacc[k] = 0.0f;
    }
    const float dlv = sdl[p0 + lane];  // lane i holds dl for row p0+i

    #pragma unroll 8
    for (int i = 0; i < 32; i++) {
        const float dl = __shfl_sync(0xffffffffu, dlv, i);
        float v[8];
        #pragma unroll
        for (int k = 0; k < 8; k++) {
            v[k] = ex2f(dl * e8[k]);
            colacc[k] += v[k];
        }
        // row-partial: tree sum of 8 values
        float r01 = v[0] + v[1];
        float r23 = v[2] + v[3];
        float r45 = v[4] + v[5];
        float r67 = v[6] + v[7];
        float r = (r01 + r23) + (r45 + r67);
        // warp reduce across 32 lanes (each lane covered distinct columns)
        r += __shfl_xor_sync(0xffffffffu, r, 16);
        r += __shfl_xor_sync(0xffffffffu, r, 8);
        r += __shfl_xor_sync(0xffffffffu, r, 4);
        r += __shfl_xor_sync(0xffffffffu, r, 2);
        r += __shfl_xor_sync(0xffffffffu, r, 1);
        if (lane == 0) srow[p0 + i] = r;
    }

    // Merge column partials across the 8 warps. Within a warp, lanes hit
    // 32 distinct banks -> conflict-free; across warps 8-way contention on
    // each address (tiny: 2048 atomics total per block).
    #pragma unroll
    for (int k = 0; k < 8; k++)
        atomicAdd(&scol[lane + 32 * k], colacc[k]);
    __syncthreads();

    const float e = se[tid];
    g_partial[(bt << 8) + tid] = e * __fdividef(scol[tid], srow[tid]);
}

// Pass 2: out[b,q] = sum_t partial[b,t,q]. Deterministic reduction.
__global__ __launch_bounds__(256) void attn_pass2(float* __restrict__ out)
{
    const int i = blockIdx.x * blockDim.x + threadIdx.x;  // 0..B*D-1
    const int b = i >> 8;
    const int q = i & 255;
    float s = 0.0f;
    #pragma unroll 8
    for (int t = 0; t < TT; t++)
        s += g_partial[((b * TT + t) << 8) + q];
    out[i] = s;
}

extern "C" void kernel_launch(void* const* d_in, const int* in_sizes, int n_in,
                              void* d_out, int out_size)
{
    const float* dec = (const float*)d_in[0];   // [8,256]
    const float* enc = (const float*)d_in[1];   // [8,128,256]
    float* out = (float*)d_out;                 // [8,256]

    attn_pass1<<<BB * TT, DD>>>(dec, enc);
    attn_pass2<<<(BB * DD) / 256, 256>>>(out);
}

// round 2
// speedup vs baseline: 1.2910x; 1.2910x over previous
#include <cuda_runtime.h>
#include <cuda_bf16.h>
#include <cstdint>

// Problem constants: B=8, T=128, D=256
#define BB 8
#define TT 128
#define DD 256

// Scratch: per-(b,t) partial contributions partial[b][t][q], then chunk sums.
__device__ float g_partial[BB * TT * DD];
__device__ float g_stage2[BB * 8 * DD];   // 8 t-chunks of 16 per b

__device__ __forceinline__ float ex2f(float x) {
    float y;
    asm("ex2.approx.f32 %0, %1;" : "=f"(y) : "f"(x));
    return y;
}

// Pass 1: one block per (b,t). M[p,q]=exp(d_p*e_q); write
// partial[b,t,q] = e_q * colsum[q] / rowsum[q].
__global__ __launch_bounds__(256) void attn_pass1(
    const float* __restrict__ dec,   // [B, D]
    const float* __restrict__ enc)   // [B, T, D]
{
    const int bt = blockIdx.x;
    const int b  = bt >> 7;
    const int tid  = threadIdx.x;
    const int warp = tid >> 5;
    const int lane = tid & 31;

    __shared__ float sdl[DD];                 // dec * log2(e)
    __shared__ float se[DD];                  // enc row
    __shared__ float scol[DD];                // col sums (atomics)
    __shared__ float spart[8 * 32 * 33];      // per-warp row partials, padded

    sdl[tid] = dec[b * DD + tid] * 1.4426950408889634f;
    se[tid]  = enc[bt * DD + tid];
    scol[tid] = 0.0f;
    __syncthreads();

    // Warp w owns rows [32w,32w+32), all 256 cols; lane owns cols {lane+32k}.
    const int p0 = warp << 5;
    float* wpart = &spart[warp * (32 * 33)];

    float e8[8], colacc[8];
    #pragma unroll
    for (int k = 0; k < 8; k++) {
        e8[k] = se[lane + 32 * k];
        colacc[k] = 0.0f;
    }
    const float dlv = sdl[p0 + lane];

    #pragma unroll 8
    for (int i = 0; i < 32; i++) {
        const float dl = __shfl_sync(0xffffffffu, dlv, i);
        float v[8];
        #pragma unroll
        for (int k = 0; k < 8; k++) {
            v[k] = ex2f(dl * e8[k]);
            colacc[k] += v[k];
        }
        // 8-col partial row sum (in-register tree), fire-and-forget STS.
        float r01 = v[0] + v[1];
        float r23 = v[2] + v[3];
        float r45 = v[4] + v[5];
        float r67 = v[6] + v[7];
        wpart[i * 33 + lane] = (r01 + r23) + (r45 + r67);
    }

    // Column partials: lanes hit 32 distinct banks; 8-way cross-warp atomics.
    #pragma unroll
    for (int k = 0; k < 8; k++)
        atomicAdd(&scol[lane + 32 * k], colacc[k]);
    __syncthreads();

    // Row sums: thread tid sums the 32 lane-partials of its row.
    // addr = w*1056 + r*33 + k -> bank (r+k)&31, conflict-free.
    const float* rp = &spart[warp * (32 * 33) + lane * 33];
    float rs = 0.0f;
    #pragma unroll
    for (int k = 0; k < 32; k++)
        rs += rp[k];

    const float e = se[tid];
    g_partial[(bt << 8) + tid] = e * __fdividef(scol[tid], rs);
}

// Pass 2a: 64 blocks = (b, chunk of 16 t). Coalesced partial reduction.
__global__ __launch_bounds__(256) void attn_pass2a()
{
    const int blk = blockIdx.x;          // 0..63
    const int b = blk >> 3;
    const int c = blk & 7;
    const int q = threadIdx.x;
    const int t0 = c << 4;
    float s = 0.0f;
    #pragma unroll
    for (int t = 0; t < 16; t++)
        s += g_partial[((b * TT + t0 + t) << 8) + q];
    g_stage2[blk * DD + q] = s;
}

// Pass 2b: 8 blocks, final 8-way reduction, coalesced.
__global__ __launch_bounds__(256) void attn_pass2b(float* __restrict__ out)
{
    const int b = blockIdx.x;
    const int q = threadIdx.x;
    float s = 0.0f;
    #pragma unroll
    for (int c = 0; c < 8; c++)
        s += g_stage2[(b * 8 + c) * DD + q];
    out[b * DD + q] = s;
}

extern "C" void kernel_launch(void* const* d_in, const int* in_sizes, int n_in,
                              void* d_out, int out_size)
{
    const float* dec = (const float*)d_in[0];   // [8,256]
    const float* enc = (const float*)d_in[1];   // [8,128,256]
    float* out = (float*)d_out;                 // [8,256]

    attn_pass1<<<BB * TT, DD>>>(dec, enc);
    attn_pass2a<<<BB * 8, DD>>>();
    attn_pass2b<<<BB, DD>>>(out);
}

// round 3
// speedup vs baseline: 2.3733x; 1.8383x over previous
#include <cuda_runtime.h>
#include <cuda_bf16.h>
#include <cstdint>

// Problem constants: B=8, T=128, D=256
#define BB 8
#define TT 128
#define DD 256
#define LOG2E 1.4426950408889634f

#define NXF 256            // F-grid intervals (257 points) over [-6,6]
#define XF_LO (-6.0f)
#define XF_SPAN 12.0f
#define NG 64              // G-grid intervals (65 points) over [dmin,dmax]

// Per-batch F tables (log2 F and Hermite tangent premultiplied by hF)
__device__ float g_LF[BB][NXF + 1];
__device__ float g_mF[BB][NXF + 1];
__device__ float g_dmin[BB];
__device__ float g_dmax[BB];
__device__ float g_partial[BB * TT * DD];

__device__ __forceinline__ float ex2f(float x) {
    float y; asm("ex2.approx.f32 %0, %1;" : "=f"(y) : "f"(x)); return y;
}
__device__ __forceinline__ float lg2f(float x) {
    float y; asm("lg2.approx.f32 %0, %1;" : "=f"(y) : "f"(x)); return y;
}
__device__ __forceinline__ float hermite(float p0, float p1, float m0, float m1, float f) {
    float f2 = f * f, f3 = f2 * f;
    return p0 * (2.f * f3 - 3.f * f2 + 1.f)
         + m0 * (f3 - 2.f * f2 + f)
         + p1 * (3.f * f2 - 2.f * f3)
         + m1 * (f3 - f2);
}

// Kernel 0: build per-batch F tables (32 blocks = 4 sub-ranges per b).
// L_F(x) = log2 sum_p 2^{dl_p x},  dL/dx = (sum_p dl_p 2^{dl_p x}) / S.
__global__ __launch_bounds__(256) void build_F(const float* __restrict__ dec)
{
    const int b   = blockIdx.x >> 2;
    const int sub = blockIdx.x & 3;
    const int tid = threadIdx.x;
    const int warp = tid >> 5;
    const int lane = tid & 31;

    __shared__ float sdl[DD];
    __shared__ float smin[DD];
    __shared__ float smax[DD];

    const float draw = dec[b * DD + tid];
    sdl[tid]  = draw * LOG2E;
    smin[tid] = draw;
    smax[tid] = draw;
    __syncthreads();

    float dl8[8];
    #pragma unroll
    for (int k = 0; k < 8; k++) dl8[k] = sdl[lane + 32 * k];

    const float hF = XF_SPAN / (float)NXF;

    // Each sub-block covers 65 grid points [sub*64, sub*64+64].
    for (int r = 0; r < 9; r++) {
        const int jl = warp + 8 * r;
        if (jl <= 64) {
            const int j = sub * 64 + jl;
            const float x = XF_LO + (float)j * hF;
            float S = 0.f, SD = 0.f;
            #pragma unroll
            for (int k = 0; k < 8; k++) {
                const float v = ex2f(x * dl8[k]);
                S += v;
                SD = fmaf(dl8[k], v, SD);
            }
            #pragma unroll
            for (int o = 16; o; o >>= 1) {
                S  += __shfl_xor_sync(0xffffffffu, S, o);
                SD += __shfl_xor_sync(0xffffffffu, SD, o);
            }
            if (lane == 0) {
                g_LF[b][j] = lg2f(S);
                g_mF[b][j] = __fdividef(SD, S) * hF;
            }
        }
    }

    // sub 0 also computes the d range for this batch.
    if (sub == 0) {
        for (int s = 128; s > 0; s >>= 1) {
            if (tid < s) {
                smin[tid] = fminf(smin[tid], smin[tid + s]);
                smax[tid] = fmaxf(smax[tid], smax[tid + s]);
            }
            __syncthreads();
        }
        if (tid == 0) {
            g_dmin[b] = smin[0];
            g_dmax[b] = smax[0];
        }
    }
}

// Pass 1: one block per (b,t). Build 65-pt Hermite table of
// L_G(y)=log2 sum_r 2^{el_r y}, then per q:
//   partial = e_q * 2^( L_F(e_q) - L_G(d_q) )
__global__ __launch_bounds__(256) void attn_pass1(
    const float* __restrict__ dec,   // [B, D]
    const float* __restrict__ enc)   // [B, T, D]
{
    const int bt = blockIdx.x;
    const int b  = bt >> 7;
    const int tid  = threadIdx.x;
    const int warp = tid >> 5;
    const int lane = tid & 31;

    __shared__ float ser[DD];        // raw e
    __shared__ float sel[DD];        // e * log2(e)
    __shared__ float sdr[DD];        // raw d
    __shared__ float sLG[NG + 1];
    __shared__ float smG[NG + 1];
    __shared__ float sLF[NXF + 1];
    __shared__ float smF[NXF + 1];

    const float eraw = enc[bt * DD + tid];
    ser[tid] = eraw;
    sel[tid] = eraw * LOG2E;
    sdr[tid] = dec[b * DD + tid];
    sLF[tid] = g_LF[b][tid];
    smF[tid] = g_mF[b][tid];
    if (tid == 0) {
        sLF[NXF] = g_LF[b][NXF];
        smF[NXF] = g_mF[b][NXF];
    }

    const float dmin = g_dmin[b];
    const float dmax = g_dmax[b];
    const float hg = (dmax - dmin) * (1.0f / (float)NG);
    const float inv_hg = __fdividef((float)NG, (dmax - dmin));
    __syncthreads();

    // Build G table: warp w handles grid points {w, w+8, ...}.
    float el8[8];
    #pragma unroll
    for (int k = 0; k < 8; k++) el8[k] = sel[lane + 32 * k];

    for (int r = 0; r < 9; r++) {
        const int j = warp + 8 * r;
        if (j <= NG) {
            const float y = dmin + (float)j * hg;
            float S = 0.f, SD = 0.f;
            #pragma unroll
            for (int k = 0; k < 8; k++) {
                const float v = ex2f(y * el8[k]);
                S += v;
                SD = fmaf(el8[k], v, SD);
            }
            #pragma unroll
            for (int o = 16; o; o >>= 1) {
                S  += __shfl_xor_sync(0xffffffffu, S, o);
                SD += __shfl_xor_sync(0xffffffffu, SD, o);
            }
            if (lane == 0) {
                sLG[j] = lg2f(S);
                smG[j] = __fdividef(SD, S) * hg;
            }
        }
    }
    __syncthreads();

    // Eval: thread tid = q.
    const float dq = sdr[tid];
    float u = (dq - dmin) * inv_hg;
    int j = (int)u;
    j = j < 0 ? 0 : (j > NG - 1 ? NG - 1 : j);
    const float f = u - (float)j;
    const float LG = hermite(sLG[j], sLG[j + 1], smG[j], smG[j + 1], f);

    const float x = ser[tid];
    float uF = (x - XF_LO) * ((float)NXF / XF_SPAN);
    int jf = (int)uF;
    jf = jf < 0 ? 0 : (jf > NXF - 1 ? NXF - 1 : jf);
    const float ff = uF - (float)jf;
    const float LF = hermite(sLF[jf], sLF[jf + 1], smF[jf], smF[jf + 1], ff);

    g_partial[(bt << 8) + tid] = x * ex2f(LF - LG);
}

// Pass 2: out[b,q] = sum_t partial[b,t,q]. 64 blocks, deterministic.
__global__ __launch_bounds__(256) void attn_pass2(float* __restrict__ out)
{
    const int blk = blockIdx.x;          // 0..63
    const int b  = blk >> 3;
    const int qg = blk & 7;
    const int lane = threadIdx.x & 31;
    const int ts   = threadIdx.x >> 5;   // 8 t-slices of 16
    const int q = (qg << 5) + lane;

    float s = 0.f;
    #pragma unroll
    for (int t = 0; t < 16; t++)
        s += g_partial[((b * TT + ts * 16 + t) << 8) + q];

    __shared__ float sp[8][32];
    sp[ts][lane] = s;
    __syncthreads();

    if (ts == 0) {
        float a = 0.f;
        #pragma unroll
        for (int k = 0; k < 8; k++) a += sp[k][lane];
        out[b * DD + q] = a;
    }
}

extern "C" void kernel_launch(void* const* d_in, const int* in_sizes, int n_in,
                              void* d_out, int out_size)
{
    const float* dec = (const float*)d_in[0];   // [8,256]
    const float* enc = (const float*)d_in[1];   // [8,128,256]
    float* out = (float*)d_out;                 // [8,256]

    build_F<<<BB * 4, DD>>>(dec);
    attn_pass1<<<BB * TT, DD>>>(dec, enc);
    attn_pass2<<<BB * 8, DD>>>(out);
}

// round 4
// speedup vs baseline: 3.5600x; 1.5000x over previous
#include <cuda_runtime.h>
#include <cuda_bf16.h>
#include <cstdint>

// Problem constants: B=8, T=128, D=256
#define BB 8
#define TT 128
#define DD 256
#define LOG2E 1.4426950408889634f

#define NXF 256            // F-grid intervals (257 points) over [-6,6]
#define XF_LO (-6.0f)
#define XF_SPAN 12.0f
#define NG 32              // G-grid intervals (33 points) over [dmin,dmax]

__device__ float g_LF[BB][NXF + 1];
__device__ float g_mF[BB][NXF + 1];
__device__ float g_dmin[BB];
__device__ float g_dmax[BB];
__device__ float g_partial[BB * TT * DD];

__device__ __forceinline__ float ex2f(float x) {
    float y; asm("ex2.approx.f32 %0, %1;" : "=f"(y) : "f"(x)); return y;
}
__device__ __forceinline__ float lg2f(float x) {
    float y; asm("lg2.approx.f32 %0, %1;" : "=f"(y) : "f"(x)); return y;
}
__device__ __forceinline__ float hermite(float p0, float p1, float m0, float m1, float f) {
    float f2 = f * f, f3 = f2 * f;
    return p0 * (2.f * f3 - 3.f * f2 + 1.f)
         + m0 * (f3 - 2.f * f2 + f)
         + p1 * (3.f * f2 - 2.f * f3)
         + m1 * (f3 - f2);
}

// Kernel 0: grid = 258 blocks. Blocks 0..256: grid point j = blockIdx.x,
// warp w computes F table entry for batch w. Block 257: per-batch d min/max.
__global__ __launch_bounds__(256) void build_F(const float* __restrict__ dec)
{
    const int j    = blockIdx.x;
    const int warp = threadIdx.x >> 5;   // = batch
    const int lane = threadIdx.x & 31;
    const int b    = warp;

    if (j <= NXF) {
        float dl[8];
        #pragma unroll
        for (int k = 0; k < 8; k++)
            dl[k] = dec[b * DD + lane + 32 * k] * LOG2E;

        const float hF = XF_SPAN / (float)NXF;
        const float x  = XF_LO + (float)j * hF;
        float S = 0.f, SD = 0.f;
        #pragma unroll
        for (int k = 0; k < 8; k++) {
            const float v = ex2f(x * dl[k]);
            S += v;
            SD = fmaf(dl[k], v, SD);
        }
        #pragma unroll
        for (int o = 16; o; o >>= 1) {
            S  += __shfl_xor_sync(0xffffffffu, S, o);
            SD += __shfl_xor_sync(0xffffffffu, SD, o);
        }
        if (lane == 0) {
            g_LF[b][j] = lg2f(S);
            g_mF[b][j] = __fdividef(SD, S) * hF;
        }
    } else {
        // d range per batch
        float lo = 1e30f, hi = -1e30f;
        #pragma unroll
        for (int k = 0; k < 8; k++) {
            const float v = dec[b * DD + lane + 32 * k];
            lo = fminf(lo, v);
            hi = fmaxf(hi, v);
        }
        #pragma unroll
        for (int o = 16; o; o >>= 1) {
            lo = fminf(lo, __shfl_xor_sync(0xffffffffu, lo, o));
            hi = fmaxf(hi, __shfl_xor_sync(0xffffffffu, hi, o));
        }
        if (lane == 0) {
            g_dmin[b] = lo;
            g_dmax[b] = hi;
        }
    }
}

// Pass 1: one block per (b,t). Build 33-pt Hermite table of
// L_G(y)=log2 sum_r 2^{el_r y}, then per q:
//   partial = e_q * 2^( L_F(e_q) - L_G(d_q) )
__global__ __launch_bounds__(256) void attn_pass1(
    const float* __restrict__ dec,   // [B, D]
    const float* __restrict__ enc)   // [B, T, D]
{
    const int bt = blockIdx.x;
    const int b  = bt >> 7;
    const int tid  = threadIdx.x;
    const int warp = tid >> 5;
    const int lane = tid & 31;

    __shared__ float ser[DD];        // raw e
    __shared__ float sel[DD];        // e * log2(e)
    __shared__ float sdr[DD];        // raw d
    __shared__ float sLG[NG + 1];
    __shared__ float smG[NG + 1];
    __shared__ float sLF[NXF + 1];
    __shared__ float smF[NXF + 1];

    const float eraw = enc[bt * DD + tid];
    ser[tid] = eraw;
    sel[tid] = eraw * LOG2E;
    sdr[tid] = dec[b * DD + tid];
    sLF[tid] = g_LF[b][tid];
    smF[tid] = g_mF[b][tid];
    if (tid == 0) {
        sLF[NXF] = g_LF[b][NXF];
        smF[NXF] = g_mF[b][NXF];
    }

    const float dmin = g_dmin[b];
    const float dmax = g_dmax[b];
    const float hg = (dmax - dmin) * (1.0f / (float)NG);
    const float inv_hg = __fdividef((float)NG, (dmax - dmin));
    __syncthreads();

    // G table: warp w handles grid points {w, w+8, w+16, w+24, (w==0: 32)}.
    float el8[8];
    #pragma unroll
    for (int k = 0; k < 8; k++) el8[k] = sel[lane + 32 * k];

    #pragma unroll
    for (int r = 0; r < 5; r++) {
        const int j = warp + 8 * r;
        if (j <= NG) {
            const float y = dmin + (float)j * hg;
            float S = 0.f, SD = 0.f;
            #pragma unroll
            for (int k = 0; k < 8; k++) {
                const float v = ex2f(y * el8[k]);
                S += v;
                SD = fmaf(el8[k], v, SD);
            }
            #pragma unroll
            for (int o = 16; o; o >>= 1) {
                S  += __shfl_xor_sync(0xffffffffu, S, o);
                SD += __shfl_xor_sync(0xffffffffu, SD, o);
            }
            if (lane == 0) {
                sLG[j] = lg2f(S);
                smG[j] = __fdividef(SD, S) * hg;
            }
        }
    }
    __syncthreads();

    // Eval: thread tid = q.
    const float dq = sdr[tid];
    float u = (dq - dmin) * inv_hg;
    int j = (int)u;
    j = j < 0 ? 0 : (j > NG - 1 ? NG - 1 : j);
    const float f = u - (float)j;
    const float LG = hermite(sLG[j], sLG[j + 1], smG[j], smG[j + 1], f);

    const float x = ser[tid];
    float uF = (x - XF_LO) * ((float)NXF / XF_SPAN);
    int jf = (int)uF;
    jf = jf < 0 ? 0 : (jf > NXF - 1 ? NXF - 1 : jf);
    const float ff = uF - (float)jf;
    const float LF = hermite(sLF[jf], sLF[jf + 1], smF[jf], smF[jf + 1], ff);

    g_partial[(bt << 8) + tid] = x * ex2f(LF - LG);
}

// Pass 2: out[b,q] = sum_t partial[b,t,q]. 64 blocks, deterministic.
__global__ __launch_bounds__(256) void attn_pass2(float* __restrict__ out)
{
    const int blk = blockIdx.x;          // 0..63
    const int b  = blk >> 3;
    const int qg = blk & 7;
    const int lane = threadIdx.x & 31;
    const int ts   = threadIdx.x >> 5;   // 8 t-slices of 16
    const int q = (qg << 5) + lane;

    float s = 0.f;
    #pragma unroll
    for (int t = 0; t < 16; t++)
        s += g_partial[((b * TT + ts * 16 + t) << 8) + q];

    __shared__ float sp[8][32];
    sp[ts][lane] = s;
    __syncthreads();

    if (ts == 0) {
        float a = 0.f;
        #pragma unroll
        for (int k = 0; k < 8; k++) a += sp[k][lane];
        out[b * DD + q] = a;
    }
}

extern "C" void kernel_launch(void* const* d_in, const int* in_sizes, int n_in,
                              void* d_out, int out_size)
{
    const float* dec = (const float*)d_in[0];   // [8,256]
    const float* enc = (const float*)d_in[1];   // [8,128,256]
    float* out = (float*)d_out;                 // [8,256]

    build_F<<<NXF + 2, DD>>>(dec);
    attn_pass1<<<BB * TT, DD>>>(dec, enc);
    attn_pass2<<<BB * 8, DD>>>(out);
}